// round 10
// baseline (speedup 1.0000x reference)
#include <cuda_runtime.h>
#include <math.h>

#define BATCH 32
#define NROI 1000
#define NCLS 81
#define MAXI 100
#define NTOT (BATCH * NROI)
#define TOTEL (NTOT * NCLS)     // total prob elements
#define BPI 32                  // blocks per image
#define RPB 32                  // ROIs per block (last block: 8)
#define BT 256
#define MCAP 768

// compacted per-image lists + tickets (zero-init; reset each run by epilogue)
__device__ float4 g_cbox[NTOT];
__device__ float4 g_cmeta[NTOT];   // {score, cls, origidx, 0}
__device__ int    g_cnt[BATCH];
__device__ int    g_done[BATCH];

struct Epi {
    float uscore[MCAP];
    short uidx[MCAP];
    float box[MCAP * 4];
    float sscore[MCAP];
    short scls[MCAP];
    short bucket[MCAP];
    unsigned char keep[MCAP];
    int   ccount[NCLS];
    int   cstart[NCLS];
    float outbuf[MAXI * 6];
};

union SmemU {
    float probs[RPB * NCLS + 8];   // 10.4 KB tile (+ shift pad)
    Epi   ep;                      // ~26.9 KB (dominates union)
};

__global__ __launch_bounds__(BT, 8)
void det_kernel(const float* __restrict__ rois,
                const float* __restrict__ probs,
                const float* __restrict__ bbox,
                const float* __restrict__ std_dev,
                float* __restrict__ out)
{
    __shared__ SmemU u;
    __shared__ int s_last;

    const int img = blockIdx.x / BPI;
    const int sub = blockIdx.x - img * BPI;
    const int t   = threadIdx.x;
    const int wid = t >> 5;
    const int lane = t & 31;

    const int row0  = sub * RPB;
    const int nrows = min(RPB, NROI - row0);          // 32, or 8 for last block
    const float4 sd = *(const float4*)std_dev;        // hoisted uniform load

    // ---------------- Phase 1a: front-batched aligned tile load (MLP=3/thread) ----
    int sh;
    {
        const int s0 = (img * NROI + row0) * NCLS;    // element offset (fits int)
        const int al = s0 & ~3;                       // 16B-aligned start
        sh = s0 - al;                                 // 0..3
        const int NEL = nrows * NCLS;
        int nvec = (sh + NEL + 3) >> 2;
        const int lim = (TOTEL - al) >> 2;            // OOB clamp at buffer end
        if (nvec > lim) nvec = lim;

        const float4* gp = (const float4*)(probs + al);
        float4* sp = (float4*)u.probs;

        const int i0 = t, i1 = t + BT, i2 = t + 2 * BT;
        const bool p0 = i0 < nvec, p1 = i1 < nvec, p2 = i2 < nvec;
        float4 a0, a1, a2;
        if (p0) a0 = gp[i0];                          // 3 independent LDG.128s
        if (p1) a1 = gp[i1];
        if (p2) a2 = gp[i2];
        if (p0) sp[i0] = a0;
        if (p1) sp[i1] = a1;
        if (p2) sp[i2] = a2;
        __syncthreads();
    }

    // ---------------- Phase 1b: 4-threads-per-ROI argmax from smem ----------------
    if (t < 4 * nrows) {                              // warp-aligned (128 or 32)
        const int rloc = t >> 2;
        const int part = t & 3;
        const float* row = u.probs + sh + rloc * NCLS;

        // column segments: 0:[0,21) 1:[21,41) 2:[41,61) 3:[61,81)
        const int cst = (part == 0) ? 0 : 21 + (part - 1) * 20;
        const int cen = (part == 0) ? 21 : cst + 20;

        // two interleaved chains (even/odd positions within segment)
        float bA = row[cst];     int iA = cst;
        float bB = row[cst + 1]; int iB = cst + 1;
        for (int c = cst + 2; c + 1 < cen; c += 2) {
            float v = row[c];
            float w = row[c + 1];
            if (v > bA) { bA = v; iA = c; }
            if (w > bB) { bB = w; iB = c + 1; }
        }
        if (((cen - cst) & 1) != 0) {                 // odd length: one tail elem
            float v = row[cen - 1];
            if (v > bA) { bA = v; iA = cen - 1; }
        }
        float best = bA; int bi = iA;
        if (bB > best || (bB == best && iB < bi)) { best = bB; bi = iB; }

        // combine 4 parts (lanes differ only in low 2 bits)
        #pragma unroll
        for (int off = 1; off <= 2; off <<= 1) {
            float ov = __shfl_xor_sync(0xffffffffu, best, off);
            int   oi = __shfl_xor_sync(0xffffffffu, bi,   off);
            if (ov > best || (ov == best && oi < bi)) { best = ov; bi = oi; }
        }

        if (part == 0 && bi > 0 && best >= 0.7f) {
            const int r = row0 + rloc;
            const size_t gri = (size_t)img * NROI + r;
            const float4 dv = *(const float4*)(bbox + (gri * NCLS + bi) * 4);
            const float4 ro = *(const float4*)(rois + gri * 4);

            float d0 = dv.x * sd.x, d1 = dv.y * sd.y, d2 = dv.z * sd.z, d3 = dv.w * sd.w;
            float hh = ro.z - ro.x;
            float ww = ro.w - ro.y;
            float cy = ro.x + 0.5f * hh + d0 * hh;
            float cx = ro.y + 0.5f * ww + d1 * ww;
            hh *= expf(d2);
            ww *= expf(d3);
            float ny1 = cy - 0.5f * hh;
            float nx1 = cx - 0.5f * ww;
            float ny2 = ny1 + hh;
            float nx2 = nx1 + ww;
            ny1 = fminf(fmaxf(ny1, 0.0f), 1.0f);
            nx1 = fminf(fmaxf(nx1, 0.0f), 1.0f);
            ny2 = fminf(fmaxf(ny2, 0.0f), 1.0f);
            nx2 = fminf(fmaxf(nx2, 0.0f), 1.0f);

            int pos = atomicAdd(&g_cnt[img], 1);
            if (pos < NROI) {
                g_cbox[img * NROI + pos]  = make_float4(ny1, nx1, ny2, nx2);
                g_cmeta[img * NROI + pos] = make_float4(best, (float)bi, (float)r, 0.0f);
            }
        }
    }

    // ---------------- Ticket: last block of this image runs the epilogue ----------
    __syncthreads();
    if (t == 0) {
        __threadfence();
        int tick = atomicAdd(&g_done[img], 1);
        s_last = (tick == BPI - 1) ? 1 : 0;
    }
    __syncthreads();
    if (!s_last) return;
    __threadfence();   // acquire

    // ---------------- Epilogue (last block per image) ----------------
    Epi& ep = u.ep;
    const int base = img * NROI;
    const int M = min(g_cnt[img], MCAP);
    const int NK = (MCAP + BT - 1) / BT;   // 3

    if (t < NCLS) ep.ccount[t] = 0;
    for (int o = t; o < MAXI * 6; o += BT) ep.outbuf[o] = 0.0f;

    float r_score[NK]; short r_cls[NK]; short r_idx[NK];
    #pragma unroll
    for (int k = 0; k < NK; ++k) {
        int e = t + k * BT;
        if (e < M) {
            float4 m = g_cmeta[base + e];
            r_score[k] = m.x;
            r_cls[k]   = (short)m.y;
            r_idx[k]   = (short)m.z;
            ep.uscore[e] = m.x;
            ep.uidx[e]   = (short)m.z;
        }
    }
    __syncthreads();

    // rank sort (score desc, orig idx asc)
    #pragma unroll
    for (int k = 0; k < NK; ++k) {
        int e = t + k * BT;
        if (e >= M) continue;
        const float ks = r_score[k];
        const short ki = r_idx[k];
        int rank = 0;
        for (int j = 0; j < M; ++j) {
            float js = ep.uscore[j];
            rank += (js > ks) || (js == ks && ep.uidx[j] < ki);
        }
        float4 bx = g_cbox[base + e];
        ep.box[rank * 4 + 0] = bx.x;
        ep.box[rank * 4 + 1] = bx.y;
        ep.box[rank * 4 + 2] = bx.z;
        ep.box[rank * 4 + 3] = bx.w;
        ep.sscore[rank] = ks;
        ep.scls[rank]   = r_cls[k];
        ep.keep[rank]   = 1;
        atomicAdd(&ep.ccount[r_cls[k]], 1);
    }
    __syncthreads();

    if (t < NCLS) {
        int st = 0;
        for (int c = 0; c < t; ++c) st += ep.ccount[c];
        ep.cstart[t] = st;
    }
    __syncthreads();

    #pragma unroll
    for (int k = 0; k < NK; ++k) {
        int r = t + k * BT;
        if (r >= M) continue;
        short c = ep.scls[r];
        int w = 0;
        for (int j = 0; j < r; ++j) w += (ep.scls[j] == c);
        ep.bucket[ep.cstart[c] + w] = (short)r;
    }
    __syncthreads();

    // warp-per-class greedy NMS (short chains)
    for (int c = wid; c < NCLS; c += 8) {
        const int st  = ep.cstart[c];
        const int cnt = ep.ccount[c];
        for (int a = 1; a < cnt; ++a) {
            int pa = ep.bucket[st + a];
            float ay1 = ep.box[pa * 4 + 0];
            float ax1 = ep.box[pa * 4 + 1];
            float ay2 = ep.box[pa * 4 + 2];
            float ax2 = ep.box[pa * 4 + 3];
            float aa = (ay2 - ay1) * (ax2 - ax1);
            bool hit = false;
            for (int q = lane; q < a; q += 32) {
                int pb = ep.bucket[st + q];
                if (ep.keep[pb]) {
                    float by1 = ep.box[pb * 4 + 0];
                    float bx1 = ep.box[pb * 4 + 1];
                    float by2 = ep.box[pb * 4 + 2];
                    float bx2 = ep.box[pb * 4 + 3];
                    float ab = (by2 - by1) * (bx2 - bx1);
                    float ih = fmaxf(fminf(ay2, by2) - fmaxf(ay1, by1), 0.0f);
                    float iw = fmaxf(fminf(ax2, bx2) - fmaxf(ax1, bx1), 0.0f);
                    float inter = ih * iw;
                    float iou = inter / fmaxf(aa + ab - inter, 1e-8f);
                    if (iou > 0.3f) hit = true;
                }
            }
            if (__ballot_sync(0xffffffffu, hit) && lane == 0) ep.keep[pa] = 0;
            __syncwarp();
        }
    }
    __syncthreads();

    // slot assignment + staged write
    #pragma unroll
    for (int k = 0; k < NK; ++k) {
        int e = t + k * BT;
        if (e >= M || !ep.keep[e]) continue;
        int slot = 0;
        for (int j = 0; j < e; ++j) slot += ep.keep[j];
        if (slot < MAXI) {
            ep.outbuf[slot * 6 + 0] = ep.box[e * 4 + 0];
            ep.outbuf[slot * 6 + 1] = ep.box[e * 4 + 1];
            ep.outbuf[slot * 6 + 2] = ep.box[e * 4 + 2];
            ep.outbuf[slot * 6 + 3] = ep.box[e * 4 + 3];
            ep.outbuf[slot * 6 + 4] = (float)ep.scls[e];
            ep.outbuf[slot * 6 + 5] = ep.sscore[e];
        }
    }
    __syncthreads();

    float* ob = out + (size_t)img * MAXI * 6;
    for (int o = t; o < MAXI * 6; o += BT) ob[o] = ep.outbuf[o];

    if (t == 0) { g_cnt[img] = 0; g_done[img] = 0; }   // reset for next replay
}

extern "C" void kernel_launch(void* const* d_in, const int* in_sizes, int n_in,
                              void* d_out, int out_size)
{
    const float* rois    = (const float*)d_in[0];
    const float* probs   = (const float*)d_in[1];
    const float* bbox    = (const float*)d_in[2];
    const float* std_dev = (const float*)d_in[3];
    float* out = (float*)d_out;
    det_kernel<<<BATCH * BPI, BT>>>(rois, probs, bbox, std_dev, out);
}

// round 11
// speedup vs baseline: 1.1593x; 1.1593x over previous
#include <cuda_runtime.h>
#include <math.h>

#define BATCH 32
#define NROI 1000
#define NCLS 81
#define MAXI 100
#define NTOT (BATCH * NROI)
#define BPI 32                  // blocks per image (kernel A)
#define RPB 32                  // ROIs per block
#define BT 256
#define BT2 256                 // kernel B threads
#define NBP 1280                // padded score-bucket count (need <=1229)

// compacted per-image lists (zero-init; g_cnt reset by kernel B each run)
__device__ float4 g_cbox[NTOT];
__device__ float4 g_cmeta[NTOT];   // {score, cls, origidx, 0}
__device__ int    g_cnt[BATCH];

// ---------------------------------------------------------------------------
// Kernel A: R9's proven phase 1 (tile load -> smem argmax -> compact valid)
// ---------------------------------------------------------------------------
__global__ __launch_bounds__(BT, 8)
void detA_kernel(const float* __restrict__ rois,
                 const float* __restrict__ probs,
                 const float* __restrict__ bbox,
                 const float* __restrict__ std_dev)
{
    __shared__ float sp[RPB * NCLS + 4];

    const int img = blockIdx.x / BPI;
    const int sub = blockIdx.x - img * BPI;
    const int t   = threadIdx.x;

    const int row0  = sub * RPB;
    const int nrows = min(RPB, NROI - row0);   // 32, or 8 for last block

    const size_t s0 = ((size_t)img * NROI + row0) * NCLS;
    const int sh  = (int)(s0 & 3);
    const int NEL = nrows * NCLS;
    const int h   = (4 - sh) & 3;

    if (t < h) sp[sh + t] = probs[s0 + t];
    const int nvec = (NEL - h) >> 2;
    const float4* gp = (const float4*)(probs + s0 + h);
    float4* spv = (float4*)(sp + sh + h);
    for (int i = t; i < nvec; i += BT) spv[i] = gp[i];
    const int tl = NEL - h - 4 * nvec;
    if (t < tl) { int e = h + 4 * nvec + t; sp[sh + e] = probs[s0 + e]; }
    __syncthreads();

    if (t < nrows) {
        const float* row = sp + sh + t * NCLS;
        float b0 = row[0]; int i0 = 0;
        float b1 = row[1]; int i1 = 1;
        float b2 = row[2]; int i2 = 2;
        #pragma unroll 13
        for (int c = 3; c < 81; c += 3) {
            float v0 = row[c];
            float v1 = row[c + 1];
            float v2 = row[c + 2];
            if (v0 > b0) { b0 = v0; i0 = c; }
            if (v1 > b1) { b1 = v1; i1 = c + 1; }
            if (v2 > b2) { b2 = v2; i2 = c + 2; }
        }
        float best = b0; int bi = i0;
        if (b1 > best || (b1 == best && i1 < bi)) { best = b1; bi = i1; }
        if (b2 > best || (b2 == best && i2 < bi)) { best = b2; bi = i2; }

        if (bi > 0 && best >= 0.7f) {
            const int r = row0 + t;
            const size_t gri = (size_t)img * NROI + r;
            const float4 sd = *(const float4*)std_dev;
            const float4 dv = *(const float4*)(bbox + (gri * NCLS + bi) * 4);
            const float4 ro = *(const float4*)(rois + gri * 4);

            float d0 = dv.x * sd.x, d1 = dv.y * sd.y, d2 = dv.z * sd.z, d3 = dv.w * sd.w;
            float hh = ro.z - ro.x;
            float ww = ro.w - ro.y;
            float cy = ro.x + 0.5f * hh + d0 * hh;
            float cx = ro.y + 0.5f * ww + d1 * ww;
            hh *= expf(d2);
            ww *= expf(d3);
            float ny1 = cy - 0.5f * hh;
            float nx1 = cx - 0.5f * ww;
            float ny2 = ny1 + hh;
            float nx2 = nx1 + ww;
            ny1 = fminf(fmaxf(ny1, 0.0f), 1.0f);
            nx1 = fminf(fmaxf(nx1, 0.0f), 1.0f);
            ny2 = fminf(fmaxf(ny2, 0.0f), 1.0f);
            nx2 = fminf(fmaxf(nx2, 0.0f), 1.0f);

            int pos = atomicAdd(&g_cnt[img], 1);
            if (pos < NROI) {
                g_cbox[img * NROI + pos]  = make_float4(ny1, nx1, ny2, nx2);
                g_cmeta[img * NROI + pos] = make_float4(best, (float)bi, (float)r, 0.0f);
            }
        }
    }
}

// ---------------------------------------------------------------------------
// Kernel B: O(M) epilogue — bucket sort, ballot class-gather, NMS, scan, emit
// ---------------------------------------------------------------------------
struct BSort { int start[NBP + 1]; int cur[NBP]; };
struct SArr  { float box[NROI * 4]; float sscore[NROI]; short scls[NROI]; };
union UB { BSort bs; SArr so; };

__global__ __launch_bounds__(BT2)
void detB_kernel(float* __restrict__ out)
{
    __shared__ float s_score[NROI];
    __shared__ short s_cls[NROI];
    __shared__ short s_idx[NROI];
    __shared__ short s_blist[NROI];        // rank -> entry
    __shared__ UB    u;                    // bucket-sort state, then sorted arrays
    __shared__ short s_cbucket[NROI];      // class-grouped sorted ranks
    __shared__ unsigned char s_keep[NROI];
    __shared__ int   s_ccount[NCLS];
    __shared__ int   s_cstart[NCLS];
    __shared__ float s_out[MAXI * 6];
    __shared__ int   s_wsum[BT2 / 32];
    __shared__ int   s_carry;

    const int b = blockIdx.x;
    const int t = threadIdx.x;
    const int wid = t >> 5;
    const int lane = t & 31;
    const int base = b * NROI;
    const int M = min(g_cnt[b], NROI);

    for (int o = t; o < MAXI * 6; o += BT2) s_out[o] = 0.0f;
    for (int i = t; i < NBP; i += BT2) u.bs.cur[i] = 0;
    if (t < NCLS) s_ccount[t] = 0;
    if (t == 0) s_carry = 0;

    // load entries
    short myb[4];   // bucket of my entries (<=4 since M<=1000, BT2=256)
    #pragma unroll
    for (int k = 0; k < 4; ++k) {
        int e = t + k * BT2;
        myb[k] = -1;
        if (e < M) {
            float4 m = g_cmeta[base + e];
            s_score[e] = m.x;
            s_cls[e]   = (short)m.y;
            s_idx[e]   = (short)m.z;
            unsigned bits = __float_as_uint(m.x);
            int bk = (int)((0x3F800000u - bits) >> 12);
            if (bk < 0) bk = 0;
            if (bk > NBP - 1) bk = NBP - 1;
            myb[k] = (short)bk;
        }
    }
    __syncthreads();
    #pragma unroll
    for (int k = 0; k < 4; ++k)
        if (myb[k] >= 0) atomicAdd(&u.bs.cur[myb[k]], 1);
    __syncthreads();

    // exclusive scan of cur[NBP] -> start[NBP], sentinel start[NBP]=M
    {
        const int PPT = NBP / BT2;   // 5
        int lpre[PPT]; int tot = 0;
        #pragma unroll
        for (int k = 0; k < PPT; ++k) { int v = u.bs.cur[t * PPT + k]; lpre[k] = tot; tot += v; }
        int inc = tot;
        #pragma unroll
        for (int off = 1; off < 32; off <<= 1) {
            int n = __shfl_up_sync(0xffffffffu, inc, off);
            if (lane >= off) inc += n;
        }
        if (lane == 31) s_wsum[wid] = inc;
        __syncthreads();
        if (wid == 0) {
            int v = (lane < BT2 / 32) ? s_wsum[lane] : 0;
            int inc2 = v;
            #pragma unroll
            for (int off = 1; off < 8; off <<= 1) {
                int n = __shfl_up_sync(0xffffffffu, inc2, off);
                if (lane >= off) inc2 += n;
            }
            if (lane < BT2 / 32) s_wsum[lane] = inc2 - v;   // exclusive warp base
        }
        __syncthreads();
        const int tbase = s_wsum[wid] + (inc - tot);
        #pragma unroll
        for (int k = 0; k < PPT; ++k) u.bs.start[t * PPT + k] = tbase + lpre[k];
        if (t == BT2 - 1) u.bs.start[NBP] = tbase + tot;    // == M
    }
    __syncthreads();
    for (int i = t; i < NBP; i += BT2) u.bs.cur[i] = 0;     // reset cursors
    __syncthreads();

    // scatter entries into bucket list (unordered within bucket)
    #pragma unroll
    for (int k = 0; k < 4; ++k) {
        int e = t + k * BT2;
        if (e < M) {
            int bk = myb[k];
            int pos = u.bs.start[bk] + atomicAdd(&u.bs.cur[bk], 1);
            s_blist[pos] = (short)e;
        }
    }
    __syncthreads();

    // within-bucket insertion sort (score desc, orig idx asc); buckets tiny
    for (int bk = t; bk < NBP; bk += BT2) {
        int st = u.bs.start[bk], en = u.bs.start[bk + 1];
        for (int i = st + 1; i < en; ++i) {
            short ent = s_blist[i];
            float sc = s_score[ent];
            short id = s_idx[ent];
            int j = i - 1;
            while (j >= st) {
                short ej = s_blist[j];
                float sj = s_score[ej];
                if (sc > sj || (sc == sj && id < s_idx[ej])) { s_blist[j + 1] = ej; --j; }
                else break;
            }
            s_blist[j + 1] = ent;
        }
    }
    __syncthreads();

    // gather into sorted arrays (overwrites bucket-sort state) + class counts
    #pragma unroll
    for (int k = 0; k < 4; ++k) {
        int r = t + k * BT2;
        if (r < M) {
            short e = s_blist[r];
            float sc = s_score[e];
            short c  = s_cls[e];
            float4 bx = g_cbox[base + e];
            u.so.box[r * 4 + 0] = bx.x;
            u.so.box[r * 4 + 1] = bx.y;
            u.so.box[r * 4 + 2] = bx.z;
            u.so.box[r * 4 + 3] = bx.w;
            u.so.sscore[r] = sc;
            u.so.scls[r]   = c;
            s_keep[r] = 1;
            atomicAdd(&s_ccount[c], 1);
        }
    }
    __syncthreads();

    if (t < NCLS) {
        int st = 0;
        for (int c = 0; c < t; ++c) st += s_ccount[c];
        s_cstart[t] = st;
    }
    __syncthreads();

    // per-class: ballot-gather members in rank order, then greedy NMS
    for (int c = wid; c < NCLS; c += BT2 / 32) {
        const int cs = s_cstart[c];
        int nmem = 0;
        for (int r0 = 0; r0 < M; r0 += 32) {
            int r = r0 + lane;
            bool m = (r < M) && (u.so.scls[r] == (short)c);
            unsigned mask = __ballot_sync(0xffffffffu, m);
            if (m) {
                int p = nmem + __popc(mask & ((1u << lane) - 1));
                s_cbucket[cs + p] = (short)r;
            }
            nmem += __popc(mask);
        }
        for (int a = 1; a < nmem; ++a) {
            int pa = s_cbucket[cs + a];
            float ay1 = u.so.box[pa * 4 + 0];
            float ax1 = u.so.box[pa * 4 + 1];
            float ay2 = u.so.box[pa * 4 + 2];
            float ax2 = u.so.box[pa * 4 + 3];
            float aa = (ay2 - ay1) * (ax2 - ax1);
            bool hit = false;
            for (int q = lane; q < a; q += 32) {
                int pb = s_cbucket[cs + q];
                if (s_keep[pb]) {
                    float by1 = u.so.box[pb * 4 + 0];
                    float bx1 = u.so.box[pb * 4 + 1];
                    float by2 = u.so.box[pb * 4 + 2];
                    float bx2 = u.so.box[pb * 4 + 3];
                    float ab = (by2 - by1) * (bx2 - bx1);
                    float ih = fmaxf(fminf(ay2, by2) - fmaxf(ay1, by1), 0.0f);
                    float iw = fmaxf(fminf(ax2, bx2) - fmaxf(ax1, bx1), 0.0f);
                    float inter = ih * iw;
                    float iou = inter / fmaxf(aa + ab - inter, 1e-8f);
                    if (iou > 0.3f) hit = true;
                }
            }
            if (__ballot_sync(0xffffffffu, hit) && lane == 0) s_keep[pa] = 0;
            __syncwarp();
        }
    }
    __syncthreads();

    // chunked block prefix scan of keep -> output slots
    for (int r0 = 0; r0 < M; r0 += BT2) {
        int r = r0 + t;
        int k = (r < M) ? (int)s_keep[r] : 0;
        unsigned mask = __ballot_sync(0xffffffffu, k != 0);
        if (lane == 0) s_wsum[wid] = __popc(mask);
        __syncthreads();
        int wbase = 0;
        for (int w2 = 0; w2 < wid; ++w2) wbase += s_wsum[w2];
        int slot = s_carry + wbase + __popc(mask & ((1u << lane) - 1));
        if (k && slot < MAXI) {
            s_out[slot * 6 + 0] = u.so.box[r * 4 + 0];
            s_out[slot * 6 + 1] = u.so.box[r * 4 + 1];
            s_out[slot * 6 + 2] = u.so.box[r * 4 + 2];
            s_out[slot * 6 + 3] = u.so.box[r * 4 + 3];
            s_out[slot * 6 + 4] = (float)u.so.scls[r];
            s_out[slot * 6 + 5] = u.so.sscore[r];
        }
        __syncthreads();
        if (t == 0) {
            int tot = 0;
            for (int w2 = 0; w2 < BT2 / 32; ++w2) tot += s_wsum[w2];
            s_carry += tot;
        }
        __syncthreads();
    }

    float* ob = out + (size_t)b * MAXI * 6;
    for (int o = t; o < MAXI * 6; o += BT2) ob[o] = s_out[o];

    if (t == 0) g_cnt[b] = 0;   // reset for next graph replay
}

extern "C" void kernel_launch(void* const* d_in, const int* in_sizes, int n_in,
                              void* d_out, int out_size)
{
    const float* rois    = (const float*)d_in[0];
    const float* probs   = (const float*)d_in[1];
    const float* bbox    = (const float*)d_in[2];
    const float* std_dev = (const float*)d_in[3];
    float* out = (float*)d_out;

    detA_kernel<<<BATCH * BPI, BT>>>(rois, probs, bbox, std_dev);
    detB_kernel<<<BATCH, BT2>>>(out);
}

// round 12
// speedup vs baseline: 1.1825x; 1.0200x over previous
#include <cuda_runtime.h>
#include <math.h>

#define BATCH 32
#define NROI 1000
#define NCLS 81
#define MAXI 100
#define NTOT (BATCH * NROI)
#define BPI 32                  // blocks per image (kernel A)
#define RPB 32                  // ROIs per block
#define BT 256
#define BT2 1024                // kernel B threads (32 warps)
#define NBP 1280                // score buckets (need 1229)

// compacted per-image lists (zero-init; g_cnt reset by kernel B each run)
__device__ float4 g_cbox[NTOT];
__device__ float4 g_cmeta[NTOT];   // {score, cls, origidx, 0}
__device__ int    g_cnt[BATCH];

// ---------------------------------------------------------------------------
// Kernel A: proven phase 1 (tile load -> smem argmax -> compact valid)
// ---------------------------------------------------------------------------
__global__ __launch_bounds__(BT, 8)
void detA_kernel(const float* __restrict__ rois,
                 const float* __restrict__ probs,
                 const float* __restrict__ bbox,
                 const float* __restrict__ std_dev)
{
    __shared__ float sp[RPB * NCLS + 4];

    const int img = blockIdx.x / BPI;
    const int sub = blockIdx.x - img * BPI;
    const int t   = threadIdx.x;

    const int row0  = sub * RPB;
    const int nrows = min(RPB, NROI - row0);

    const size_t s0 = ((size_t)img * NROI + row0) * NCLS;
    const int sh  = (int)(s0 & 3);
    const int NEL = nrows * NCLS;
    const int h   = (4 - sh) & 3;

    if (t < h) sp[sh + t] = probs[s0 + t];
    const int nvec = (NEL - h) >> 2;
    const float4* gp = (const float4*)(probs + s0 + h);
    float4* spv = (float4*)(sp + sh + h);
    for (int i = t; i < nvec; i += BT) spv[i] = gp[i];
    const int tl = NEL - h - 4 * nvec;
    if (t < tl) { int e = h + 4 * nvec + t; sp[sh + e] = probs[s0 + e]; }
    __syncthreads();

    if (t < nrows) {
        const float* row = sp + sh + t * NCLS;
        float b0 = row[0]; int i0 = 0;
        float b1 = row[1]; int i1 = 1;
        float b2 = row[2]; int i2 = 2;
        #pragma unroll 13
        for (int c = 3; c < 81; c += 3) {
            float v0 = row[c];
            float v1 = row[c + 1];
            float v2 = row[c + 2];
            if (v0 > b0) { b0 = v0; i0 = c; }
            if (v1 > b1) { b1 = v1; i1 = c + 1; }
            if (v2 > b2) { b2 = v2; i2 = c + 2; }
        }
        float best = b0; int bi = i0;
        if (b1 > best || (b1 == best && i1 < bi)) { best = b1; bi = i1; }
        if (b2 > best || (b2 == best && i2 < bi)) { best = b2; bi = i2; }

        if (bi > 0 && best >= 0.7f) {
            const int r = row0 + t;
            const size_t gri = (size_t)img * NROI + r;
            const float4 sd = *(const float4*)std_dev;
            const float4 dv = *(const float4*)(bbox + (gri * NCLS + bi) * 4);
            const float4 ro = *(const float4*)(rois + gri * 4);

            float d0 = dv.x * sd.x, d1 = dv.y * sd.y, d2 = dv.z * sd.z, d3 = dv.w * sd.w;
            float hh = ro.z - ro.x;
            float ww = ro.w - ro.y;
            float cy = ro.x + 0.5f * hh + d0 * hh;
            float cx = ro.y + 0.5f * ww + d1 * ww;
            hh *= expf(d2);
            ww *= expf(d3);
            float ny1 = cy - 0.5f * hh;
            float nx1 = cx - 0.5f * ww;
            float ny2 = ny1 + hh;
            float nx2 = nx1 + ww;
            ny1 = fminf(fmaxf(ny1, 0.0f), 1.0f);
            nx1 = fminf(fmaxf(nx1, 0.0f), 1.0f);
            ny2 = fminf(fmaxf(ny2, 0.0f), 1.0f);
            nx2 = fminf(fmaxf(nx2, 0.0f), 1.0f);

            int pos = atomicAdd(&g_cnt[img], 1);
            if (pos < NROI) {
                g_cbox[img * NROI + pos]  = make_float4(ny1, nx1, ny2, nx2);
                g_cmeta[img * NROI + pos] = make_float4(best, (float)bi, (float)r, 0.0f);
            }
        }
    }
}

// ---------------------------------------------------------------------------
// Kernel B: wide O(M) epilogue — bucket sort, match_any class-gather, NMS, emit
// ---------------------------------------------------------------------------
struct BSort { int start[NBP + 1]; int cur[NBP]; };
struct SArr  { float box[NROI * 4]; float sscore[NROI]; short scls[NROI]; };
union UB { BSort bs; SArr so; };

__global__ __launch_bounds__(BT2)
void detB_kernel(float* __restrict__ out)
{
    __shared__ float s_score[NROI];
    __shared__ short s_cls[NROI];
    __shared__ short s_idx[NROI];
    __shared__ short s_blist[NROI];
    __shared__ UB    u;
    __shared__ short s_cbucket[NROI];
    __shared__ unsigned char s_keep[NROI];
    __shared__ int   s_ccount[NCLS];
    __shared__ int   s_cstart[NCLS];
    __shared__ int   s_ccur[NCLS];
    __shared__ float s_out[MAXI * 6];
    __shared__ int   s_wsum[BT2 / 32];

    const int b = blockIdx.x;
    const int t = threadIdx.x;
    const int wid = t >> 5;
    const int lane = t & 31;
    const int base = b * NROI;
    const int M = min(g_cnt[b], NROI);

    for (int o = t; o < MAXI * 6; o += BT2) s_out[o] = 0.0f;
    for (int i = t; i < NBP; i += BT2) u.bs.cur[i] = 0;
    if (t < NCLS) { s_ccount[t] = 0; s_ccur[t] = 0; }

    // ---- load entries (one per thread; M <= 1000 < BT2) + histogram ----
    int myb = -1;
    if (t < M) {
        float4 m = g_cmeta[base + t];
        s_score[t] = m.x;
        s_cls[t]   = (short)m.y;
        s_idx[t]   = (short)m.z;
        unsigned bits = __float_as_uint(m.x);
        int bk = (int)((0x3F800000u - bits) >> 12);
        bk = max(0, min(NBP - 1, bk));
        myb = bk;
    }
    __syncthreads();
    if (myb >= 0) atomicAdd(&u.bs.cur[myb], 1);
    __syncthreads();

    // ---- exclusive scan of cur[NBP] -> start[] (first 256 threads) ----
    if (t < 256) {
        const int PPT = NBP / 256;   // 5
        int lpre[PPT]; int tot = 0;
        #pragma unroll
        for (int k = 0; k < PPT; ++k) { int v = u.bs.cur[t * PPT + k]; lpre[k] = tot; tot += v; }
        int inc = tot;
        #pragma unroll
        for (int off = 1; off < 32; off <<= 1) {
            int n = __shfl_up_sync(0xffffffffu, inc, off);
            if (lane >= off) inc += n;
        }
        if (lane == 31) s_wsum[wid] = inc;
        __syncwarp();
        // cross-warp (8 warps) combine done after barrier below
        // store partial; finish after a block sync
        // (we need a block-level sync; do it outside)
        // stash inc-tot (exclusive within warp) temporarily in start
        u.bs.start[t] = inc - tot;   // exclusive-in-warp prefix
        #pragma unroll
        for (int k = 0; k < PPT; ++k) u.bs.start[256 + t * PPT + k] = lpre[k];  // stage lpre? NO — overlap!
    }
    __syncthreads();
    // The staging above would collide with start[] layout; redo scan simply:
    // (correctness-first: recompute cleanly)
    if (t < 256) {
        const int PPT = NBP / 256;
        // recompute local prefix from cur[]
        int lpre[PPT]; int tot = 0;
        #pragma unroll
        for (int k = 0; k < PPT; ++k) { int v = u.bs.cur[t * PPT + k]; lpre[k] = tot; tot += v; }
        int inc = tot;
        #pragma unroll
        for (int off = 1; off < 32; off <<= 1) {
            int n = __shfl_up_sync(0xffffffffu, inc, off);
            if (lane >= off) inc += n;
        }
        if (lane == 31) s_wsum[wid] = inc;
        __syncwarp();
        int wbase = 0;
        for (int w2 = 0; w2 < wid; ++w2) wbase += s_wsum[w2];   // reads own-warp-group sums
        // NOTE: s_wsum written by warps 0..7 only; all t<256 read after syncwarp
        // is insufficient cross-warp — replaced by barrier below.
        u.bs.start[NBP] = 0;  // placeholder; fixed after barrier
        // stage per-thread values in registers via shared round 2:
        s_blist[t] = 0;       // no-op touch to keep compiler honest
        // defer final write: store tbase components
        u.bs.cur[t] = inc - tot;   // reuse cur[0..255] as exclusive-in-warp prefix
        // lpre recomputed again after barrier (cheap)
    }
    __syncthreads();
    if (t < 256) {
        const int PPT = NBP / 256;
        int wbase = 0;
        for (int w2 = 0; w2 < (t >> 5); ++w2) wbase += s_wsum[w2];
        const int exwarp = u.bs.cur[t];
        // recompute lpre from... cur was clobbered for t<256! Buckets t*PPT..: indices 0..1279,
        // cur[0..255] clobbered — but those buckets' counts were consumed into lpre before
        // clobber, and lpre must be recomputed. Avoid: recompute from histogram is impossible.
        // => use start[] (untouched except [NBP]) to stage lpre in pass 1 instead.
        (void)PPT; (void)wbase; (void)exwarp;
    }
    __syncthreads();
    // --- Clean final scan implementation (single source of truth) ---
    // Rebuild histogram (cur[0..255] were clobbered): cheap, atomics again.
    for (int i = t; i < NBP; i += BT2) u.bs.cur[i] = 0;
    __syncthreads();
    if (myb >= 0) atomicAdd(&u.bs.cur[myb], 1);
    __syncthreads();
    if (t < 256) {
        const int PPT = NBP / 256;
        int lpre[PPT]; int tot = 0;
        #pragma unroll
        for (int k = 0; k < PPT; ++k) { int v = u.bs.cur[t * PPT + k]; lpre[k] = tot; tot += v; }
        int inc = tot;
        #pragma unroll
        for (int off = 1; off < 32; off <<= 1) {
            int n = __shfl_up_sync(0xffffffffu, inc, off);
            if (lane >= off) inc += n;
        }
        if (lane == 31) s_wsum[wid] = inc;
        // write exclusive-in-warp + lpre into registers; finish after block sync
        // (store start AFTER computing wbase post-barrier; keep lpre in regs)
        __syncthreads();
        int wbase = 0;
        for (int w2 = 0; w2 < wid; ++w2) wbase += s_wsum[w2];
        const int tbase = wbase + (inc - tot);
        #pragma unroll
        for (int k = 0; k < PPT; ++k) u.bs.start[t * PPT + k] = tbase + lpre[k];
        if (t == 255) u.bs.start[NBP] = tbase + tot;
    } else {
        __syncthreads();
    }
    __syncthreads();
    for (int i = t; i < NBP; i += BT2) u.bs.cur[i] = 0;
    __syncthreads();

    // ---- scatter into bucket list ----
    if (t < M) {
        int pos = u.bs.start[myb] + atomicAdd(&u.bs.cur[myb], 1);
        s_blist[pos] = (short)t;
    }
    __syncthreads();

    // ---- within-bucket insertion sort (score desc, idx asc) ----
    for (int bk = t; bk < NBP; bk += BT2) {
        int st = u.bs.start[bk], en = u.bs.start[bk + 1];
        for (int i = st + 1; i < en; ++i) {
            short ent = s_blist[i];
            float sc = s_score[ent];
            short id = s_idx[ent];
            int j = i - 1;
            while (j >= st) {
                short ej = s_blist[j];
                float sj = s_score[ej];
                if (sc > sj || (sc == sj && id < s_idx[ej])) { s_blist[j + 1] = ej; --j; }
                else break;
            }
            s_blist[j + 1] = ent;
        }
    }
    __syncthreads();

    // ---- gather sorted arrays (overwrites bucket state) + class counts ----
    if (t < M) {
        short e = s_blist[t];
        float sc = s_score[e];
        short c  = s_cls[e];
        float4 bx = g_cbox[base + e];
        u.so.box[t * 4 + 0] = bx.x;
        u.so.box[t * 4 + 1] = bx.y;
        u.so.box[t * 4 + 2] = bx.z;
        u.so.box[t * 4 + 3] = bx.w;
        u.so.sscore[t] = sc;
        u.so.scls[t]   = c;
        s_keep[t] = 1;
        atomicAdd(&s_ccount[c], 1);
    }
    __syncthreads();

    if (t < NCLS) {
        int st = 0;
        for (int c = 0; c < t; ++c) st += s_ccount[c];
        s_cstart[t] = st;
    }
    __syncthreads();

    // ---- single-warp stable class scatter via match_any (O(M/32) chunks) ----
    if (wid == 0) {
        int r = lane;
        int cn = (r < M) ? (int)u.so.scls[r] : (NCLS + lane);   // prefetch chunk 0
        for (int c0 = 0; c0 < M; c0 += 32) {
            int c = cn;
            int rn = c0 + 32 + lane;                            // prefetch next chunk
            cn = (rn < M) ? (int)u.so.scls[rn] : (NCLS + lane);
            bool v = (c0 + lane) < M;
            unsigned mask = __match_any_sync(0xffffffffu, c);
            int leader = __ffs(mask) - 1;
            int bpos = 0;
            if (lane == leader && v) bpos = atomicAdd(&s_ccur[c], __popc(mask));
            bpos = __shfl_sync(0xffffffffu, bpos, leader);
            if (v) s_cbucket[s_cstart[c] + bpos + __popc(mask & ((1u << lane) - 1))]
                     = (short)(c0 + lane);
        }
    }
    __syncthreads();

    // ---- warp-per-class greedy NMS (32 warps) ----
    for (int c = wid; c < NCLS; c += BT2 / 32) {
        const int cs = s_cstart[c];
        const int cnt = s_ccount[c];
        for (int a = 1; a < cnt; ++a) {
            int pa = s_cbucket[cs + a];
            float ay1 = u.so.box[pa * 4 + 0];
            float ax1 = u.so.box[pa * 4 + 1];
            float ay2 = u.so.box[pa * 4 + 2];
            float ax2 = u.so.box[pa * 4 + 3];
            float aa = (ay2 - ay1) * (ax2 - ax1);
            bool hit = false;
            for (int q = lane; q < a; q += 32) {
                int pb = s_cbucket[cs + q];
                if (s_keep[pb]) {
                    float by1 = u.so.box[pb * 4 + 0];
                    float bx1 = u.so.box[pb * 4 + 1];
                    float by2 = u.so.box[pb * 4 + 2];
                    float bx2 = u.so.box[pb * 4 + 3];
                    float ab = (by2 - by1) * (bx2 - bx1);
                    float ih = fmaxf(fminf(ay2, by2) - fmaxf(ay1, by1), 0.0f);
                    float iw = fmaxf(fminf(ax2, bx2) - fmaxf(ax1, bx1), 0.0f);
                    float inter = ih * iw;
                    float iou = inter / fmaxf(aa + ab - inter, 1e-8f);
                    if (iou > 0.3f) hit = true;
                }
            }
            if (__ballot_sync(0xffffffffu, hit) && lane == 0) s_keep[pa] = 0;
            __syncwarp();
        }
    }
    __syncthreads();

    // ---- single-pass slot scan (M <= 1000 < 1024) + staged write ----
    {
        int k = (t < M) ? (int)s_keep[t] : 0;
        unsigned mask = __ballot_sync(0xffffffffu, k != 0);
        if (lane == 0) s_wsum[wid] = __popc(mask);
        __syncthreads();
        int wbase = 0;
        for (int w2 = 0; w2 < wid; ++w2) wbase += s_wsum[w2];
        int slot = wbase + __popc(mask & ((1u << lane) - 1));
        if (k && slot < MAXI) {
            s_out[slot * 6 + 0] = u.so.box[t * 4 + 0];
            s_out[slot * 6 + 1] = u.so.box[t * 4 + 1];
            s_out[slot * 6 + 2] = u.so.box[t * 4 + 2];
            s_out[slot * 6 + 3] = u.so.box[t * 4 + 3];
            s_out[slot * 6 + 4] = (float)u.so.scls[t];
            s_out[slot * 6 + 5] = u.so.sscore[t];
        }
    }
    __syncthreads();

    float* ob = out + (size_t)b * MAXI * 6;
    for (int o = t; o < MAXI * 6; o += BT2) ob[o] = s_out[o];

    if (t == 0) g_cnt[b] = 0;   // reset for next graph replay
}

extern "C" void kernel_launch(void* const* d_in, const int* in_sizes, int n_in,
                              void* d_out, int out_size)
{
    const float* rois    = (const float*)d_in[0];
    const float* probs   = (const float*)d_in[1];
    const float* bbox    = (const float*)d_in[2];
    const float* std_dev = (const float*)d_in[3];
    float* out = (float*)d_out;

    detA_kernel<<<BATCH * BPI, BT>>>(rois, probs, bbox, std_dev);
    detB_kernel<<<BATCH, BT2>>>(out);
}